// round 14
// baseline (speedup 1.0000x reference)
#include <cuda_runtime.h>
#include <cuda_bf16.h>
#include <cuda_fp16.h>
#include <cstdint>

#define D 128
#define NMAX 100000
#define EMAX 800000
#define VMAX 1000
#define SCAN_ITEMS 1024
#define SCAN_MAXB  ((NMAX + SCAN_ITEMS - 1) / SCAN_ITEMS + 1)

// Scratch (allocation-free rule: device globals)
__device__ __align__(16) __half g_bufAh[NMAX * D];  // g2 vectors, fp16
__device__ __align__(16) __half g_bufCh[NMAX * D];  // h1 (post relu), fp16
__device__ __align__(16) __half g_embWh[VMAX * D];  // emb @ W1, fp16
__device__ __align__(16) __half g_W2t[D * D];       // W2 transposed [n][k], fp16
__device__ float g_dinv[NMAX];
__device__ int2  g_xd[NMAX];                        // packed {x[i], bits(dinv[i])}
__device__ int   g_deg[NMAX];
__device__ int   g_rowstart[NMAX + 1];
__device__ int   g_pos[EMAX];                       // per-edge rank within dst bucket
__device__ int   g_csr[EMAX];                       // src ids grouped by dst
__device__ int   g_bsum[SCAN_MAXB];
__device__ int   g_bar_count = 0;
__device__ int   g_bar_gen   = 0;

// ---------------- software grid barrier (all blocks resident: grid <= 148) ----------------
__device__ __forceinline__ void grid_barrier(int nblocks) {
    __syncthreads();
    if (threadIdx.x == 0) {
        int gen = *((volatile int*)&g_bar_gen);
        __threadfence();
        if (atomicAdd(&g_bar_count, 1) == nblocks - 1) {
            g_bar_count = 0;
            __threadfence();
            atomicExch(&g_bar_gen, gen + 1);
        } else {
            while (*((volatile int*)&g_bar_gen) == gen) { }
            __threadfence();
        }
    }
    __syncthreads();
}

// ---------------- degree count + per-edge rank (2 edges/thread) ----------------
__global__ void k_deg(const int* __restrict__ dst, int e) {
    int i0 = (blockIdx.x * blockDim.x + threadIdx.x) * 2;
    if (i0 + 1 < e) {
        int2 d2 = *(const int2*)(dst + i0);
        int p0 = atomicAdd(&g_deg[d2.x], 1);
        int p1 = atomicAdd(&g_deg[d2.y], 1);
        *(int2*)(g_pos + i0) = make_int2(p0, p1);
    } else if (i0 < e) {
        g_pos[i0] = atomicAdd(&g_deg[dst[i0]], 1);
    }
}

__device__ __forceinline__ int4 load_deg4(int idx, int n) {
    int4 v = make_int4(0, 0, 0, 0);
    if (idx + 3 < n)      v = ((const int4*)g_deg)[idx >> 2];
    else {
        if (idx + 0 < n) v.x = g_deg[idx + 0];
        if (idx + 1 < n) v.y = g_deg[idx + 1];
        if (idx + 2 < n) v.z = g_deg[idx + 2];
        if (idx + 3 < n) v.w = g_deg[idx + 3];
    }
    return v;
}

// ---------------- fused: embW prep + W2t prep + full scan (rowstart/dinv/xd) ----------------
// grid = nb (= ceil(n/1024) = 98 <= 148) blocks x 256 threads; software grid barrier inside.
__global__ void __launch_bounds__(256) k_scanprep(
    const float* __restrict__ emb, const float* __restrict__ W1,
    const float* __restrict__ W2, const int* __restrict__ x,
    int n, int e, int V, int nb) {
    int bid = blockIdx.x;
    int t = threadIdx.x;
    __shared__ float se[2 * D];
    __shared__ int sp[256];
    __shared__ int sred[8];
    __shared__ int soff;

    // --- phase 0a: embW = emb @ W1 -> fp16, 2 rows per block-iteration ---
    for (int rp = bid; rp * 2 < V; rp += nb) {
        int r0 = rp * 2;
        {
            int r = r0 + (t >> 7);
            se[t] = (r < V) ? emb[r * D + (t & 127)] : 0.f;
        }
        __syncthreads();
        int rr = t >> 7, c = t & 127;
        float acc = 0.f;
#pragma unroll 4
        for (int k = 0; k < D; k++) acc = fmaf(se[rr * D + k], __ldg(&W1[k * D + c]), acc);
        int r = r0 + rr;
        if (r < V) g_embWh[r * D + c] = __float2half(acc);
        __syncthreads();
    }
    // --- phase 0b: W2 -> fp16 transposed ---
    for (int idx = bid * 256 + t; idx < D * D; idx += nb * 256) {
        int k = idx >> 7, nn = idx & 127;
        g_W2t[nn * D + k] = __float2half(W2[idx]);
    }
    // --- phase 0c: per-chunk deg sums (deg4 kept in regs for phase 2) ---
    int idx0 = bid * SCAN_ITEMS + t * 4;
    int4 v = load_deg4(idx0, n);
    {
        int s = v.x + v.y + v.z + v.w;
#pragma unroll
        for (int off = 16; off > 0; off >>= 1) s += __shfl_down_sync(~0u, s, off);
        if ((t & 31) == 0) sred[t >> 5] = s;
        __syncthreads();
        if (t < 8) {
            int r = sred[t];
#pragma unroll
            for (int off = 4; off > 0; off >>= 1) r += __shfl_down_sync(0xFFu, r, off);
            if (t == 0) g_bsum[bid] = r;
        }
    }

    grid_barrier(nb);

    // --- phase 1: block offset = sum of bsum[0..bid) ---
    {
        int val = (t < bid) ? g_bsum[t] : 0;   // bid <= 97 < 256
#pragma unroll
        for (int off = 16; off > 0; off >>= 1) val += __shfl_down_sync(~0u, val, off);
        if ((t & 31) == 0) sred[t >> 5] = val;
        __syncthreads();
        if (t == 0) {
            int s = 0;
#pragma unroll
            for (int w = 0; w < 8; w++) s += sred[w];
            soff = s;
        }
        __syncthreads();
    }
    int blockOff = soff;

    // --- phase 2: local exclusive scan + outputs (rowstart, dinv, xd) ---
    int s = v.x + v.y + v.z + v.w;
    sp[t] = s;
    __syncthreads();
    for (int off = 1; off < 256; off <<= 1) {
        int u = (t >= off) ? sp[t - off] : 0;
        __syncthreads();
        sp[t] += u;
        __syncthreads();
    }
    int pre = blockOff + ((t == 0) ? 0 : sp[t - 1]);
    int idx = idx0;
    if (idx + 0 < n) { float di = rsqrtf((float)(v.x + 1)); g_rowstart[idx + 0] = pre; pre += v.x; g_dinv[idx + 0] = di; g_xd[idx + 0] = make_int2(x[idx + 0], __float_as_int(di)); }
    if (idx + 1 < n) { float di = rsqrtf((float)(v.y + 1)); g_rowstart[idx + 1] = pre; pre += v.y; g_dinv[idx + 1] = di; g_xd[idx + 1] = make_int2(x[idx + 1], __float_as_int(di)); }
    if (idx + 2 < n) { float di = rsqrtf((float)(v.z + 1)); g_rowstart[idx + 2] = pre; pre += v.z; g_dinv[idx + 2] = di; g_xd[idx + 2] = make_int2(x[idx + 2], __float_as_int(di)); }
    if (idx + 3 < n) { float di = rsqrtf((float)(v.w + 1)); g_rowstart[idx + 3] = pre;             g_dinv[idx + 3] = di; g_xd[idx + 3] = make_int2(x[idx + 3], __float_as_int(di)); }
    if (bid == 0 && t == 0) g_rowstart[n] = e;
}

// ---------------- CSR fill: NO atomics (rank precomputed in k_deg) ----------------
__global__ void k_fill(const int* __restrict__ src, const int* __restrict__ dst, int e) {
    int i = blockIdx.x * blockDim.x + threadIdx.x;
    if (i < e) {
        int d = dst[i];
        g_csr[g_rowstart[d] + g_pos[i]] = src[i];
    }
}

// ---------------- helpers ----------------
__device__ __forceinline__ float4 h4_to_f4(uint2 u) {
    __half2 h01 = *(__half2*)&u.x;
    __half2 h23 = *(__half2*)&u.y;
    float2 f01 = __half22float2(h01);
    float2 f23 = __half22float2(h23);
    return make_float4(f01.x, f01.y, f23.x, f23.y);
}

// ---------------- fused layer1: gather-from-embW(fp16) + aggregate + finalize -> fp16 ----------------
__global__ void k_agg1(const float* __restrict__ b1, int n) {
    int wid  = (blockIdx.x * blockDim.x + threadIdx.x) >> 5;
    int lane = threadIdx.x & 31;
    if (wid >= n) return;
    const uint2* EW = (const uint2*)g_embWh;
    int2 sxd = g_xd[wid];
    float dis = __int_as_float(sxd.y);
    float4 e0 = h4_to_f4(EW[sxd.x * 32 + lane]);
    float4 A1 = make_float4(e0.x * dis, e0.y * dis, e0.z * dis, e0.w * dis);
    float4 A2 = make_float4(0.f, 0.f, 0.f, 0.f);
    float4 A3 = make_float4(0.f, 0.f, 0.f, 0.f);
    float4 A4 = make_float4(0.f, 0.f, 0.f, 0.f);
    int rs = g_rowstart[wid], re = g_rowstart[wid + 1];
    int i = rs;
    for (; i + 3 < re; i += 4) {
        int2 xd0 = g_xd[g_csr[i]];
        int2 xd1 = g_xd[g_csr[i + 1]];
        int2 xd2 = g_xd[g_csr[i + 2]];
        int2 xd3 = g_xd[g_csr[i + 3]];
        float4 a = h4_to_f4(EW[xd0.x * 32 + lane]);
        float4 b = h4_to_f4(EW[xd1.x * 32 + lane]);
        float4 c = h4_to_f4(EW[xd2.x * 32 + lane]);
        float4 d = h4_to_f4(EW[xd3.x * 32 + lane]);
        float d0 = __int_as_float(xd0.y), d1 = __int_as_float(xd1.y);
        float d2 = __int_as_float(xd2.y), d3 = __int_as_float(xd3.y);
        A1.x = fmaf(a.x, d0, A1.x); A1.y = fmaf(a.y, d0, A1.y); A1.z = fmaf(a.z, d0, A1.z); A1.w = fmaf(a.w, d0, A1.w);
        A2.x = fmaf(b.x, d1, A2.x); A2.y = fmaf(b.y, d1, A2.y); A2.z = fmaf(b.z, d1, A2.z); A2.w = fmaf(b.w, d1, A2.w);
        A3.x = fmaf(c.x, d2, A3.x); A3.y = fmaf(c.y, d2, A3.y); A3.z = fmaf(c.z, d2, A3.z); A3.w = fmaf(c.w, d2, A3.w);
        A4.x = fmaf(d.x, d3, A4.x); A4.y = fmaf(d.y, d3, A4.y); A4.z = fmaf(d.z, d3, A4.z); A4.w = fmaf(d.w, d3, A4.w);
    }
    for (; i < re; i++) {
        int2 xd0 = g_xd[g_csr[i]];
        float d0 = __int_as_float(xd0.y);
        float4 a = h4_to_f4(EW[xd0.x * 32 + lane]);
        A1.x = fmaf(a.x, d0, A1.x); A1.y = fmaf(a.y, d0, A1.y);
        A1.z = fmaf(a.z, d0, A1.z); A1.w = fmaf(a.w, d0, A1.w);
    }
    A1.x += A2.x + A3.x + A4.x; A1.y += A2.y + A3.y + A4.y;
    A1.z += A2.z + A3.z + A4.z; A1.w += A2.w + A3.w + A4.w;
    float4 b = ((const float4*)b1)[lane];
    float hx = fmaxf(A1.x * dis + b.x, 0.f);
    float hy = fmaxf(A1.y * dis + b.y, 0.f);
    float hz = fmaxf(A1.z * dis + b.z, 0.f);
    float hw = fmaxf(A1.w * dis + b.w, 0.f);
    __half2 lo = __floats2half2_rn(hx, hy);
    __half2 hi = __floats2half2_rn(hz, hw);
    uint2 o; o.x = *(uint32_t*)&lo; o.y = *(uint32_t*)&hi;
    ((uint2*)g_bufCh)[wid * 32 + lane] = o;
}

// ---------------- fp16 tensor-core GEMM: g2 = (h1 @ W2) * dinv -> fp16 ----------------
#define SR 72
__global__ void __launch_bounds__(256, 2) k_gemm(int n) {
    __shared__ __half sH[128 * SR];
    __shared__ __half sWt[128 * SR];
    int t = threadIdx.x;
    int warp = t >> 5, lane = t & 31;
    int g = lane >> 2, tg = lane & 3;
    int row0 = blockIdx.x * 128;
    int warpRow = warp * 16;

    float c[16][4];
#pragma unroll
    for (int nt = 0; nt < 16; nt++)
#pragma unroll
        for (int j = 0; j < 4; j++) c[nt][j] = 0.f;

    const uint4* Hv = (const uint4*)g_bufCh;
    const uint4* Wv = (const uint4*)g_W2t;

    for (int kc = 0; kc < 2; kc++) {
#pragma unroll
        for (int i = 0; i < 4; i++) {
            int idx = t + i * 256;
            int nn = idx >> 3, q = idx & 7;
            *(uint4*)&sWt[nn * SR + q * 8] = Wv[nn * 16 + kc * 8 + q];
        }
#pragma unroll
        for (int i = 0; i < 4; i++) {
            int idx = t + i * 256;
            int r = idx >> 3, q = idx & 7;
            int grow = row0 + r;
            uint4 v = make_uint4(0, 0, 0, 0);
            if (grow < n) v = Hv[grow * 16 + kc * 8 + q];
            *(uint4*)&sH[r * SR + q * 8] = v;
        }
        __syncthreads();
#pragma unroll
        for (int ks = 0; ks < 4; ks++) {
            int k0 = ks * 16;
            uint32_t a0 = *(uint32_t*)&sH[(warpRow + g)     * SR + k0 + 2 * tg];
            uint32_t a1 = *(uint32_t*)&sH[(warpRow + g + 8) * SR + k0 + 2 * tg];
            uint32_t a2 = *(uint32_t*)&sH[(warpRow + g)     * SR + k0 + 2 * tg + 8];
            uint32_t a3 = *(uint32_t*)&sH[(warpRow + g + 8) * SR + k0 + 2 * tg + 8];
#pragma unroll
            for (int nt = 0; nt < 16; nt++) {
                uint32_t b0 = *(uint32_t*)&sWt[(nt * 8 + g) * SR + k0 + 2 * tg];
                uint32_t b1 = *(uint32_t*)&sWt[(nt * 8 + g) * SR + k0 + 2 * tg + 8];
                asm volatile(
                    "mma.sync.aligned.m16n8k16.row.col.f32.f16.f16.f32 "
                    "{%0,%1,%2,%3}, {%4,%5,%6,%7}, {%8,%9}, {%0,%1,%2,%3};"
                    : "+f"(c[nt][0]), "+f"(c[nt][1]), "+f"(c[nt][2]), "+f"(c[nt][3])
                    : "r"(a0), "r"(a1), "r"(a2), "r"(a3), "r"(b0), "r"(b1));
            }
        }
        __syncthreads();
    }
    int r0 = row0 + warpRow + g;
    int r1 = r0 + 8;
    float di0 = (r0 < n) ? g_dinv[r0] : 0.f;
    float di1 = (r1 < n) ? g_dinv[r1] : 0.f;
    __half2* Bh = (__half2*)g_bufAh;
#pragma unroll
    for (int nt = 0; nt < 16; nt++) {
        int col = nt * 8 + tg * 2;
        if (r0 < n) Bh[(r0 * D + col) >> 1] = __floats2half2_rn(c[nt][0] * di0, c[nt][1] * di0);
        if (r1 < n) Bh[(r1 * D + col) >> 1] = __floats2half2_rn(c[nt][2] * di1, c[nt][3] * di1);
    }
}

// ---------------- fused aggregate layer2 (fp16 L2-only reads, 4-way) + final dot ----------------
__global__ void k_agg2(const float* __restrict__ b2, const float* __restrict__ Wf,
                       const float* __restrict__ bf, float* __restrict__ out, int n) {
    int wid  = (blockIdx.x * blockDim.x + threadIdx.x) >> 5;
    int lane = threadIdx.x & 31;
    if (wid >= n) return;
    const uint2* G = (const uint2*)g_bufAh;
    float4 A1 = h4_to_f4(__ldcg(&G[wid * 32 + lane]));
    float4 A2 = make_float4(0.f, 0.f, 0.f, 0.f);
    float4 A3 = make_float4(0.f, 0.f, 0.f, 0.f);
    float4 A4 = make_float4(0.f, 0.f, 0.f, 0.f);
    int rs = g_rowstart[wid], re = g_rowstart[wid + 1];
    int i = rs;
    for (; i + 3 < re; i += 4) {
        float4 a = h4_to_f4(__ldcg(&G[g_csr[i]     * 32 + lane]));
        float4 b = h4_to_f4(__ldcg(&G[g_csr[i + 1] * 32 + lane]));
        float4 c = h4_to_f4(__ldcg(&G[g_csr[i + 2] * 32 + lane]));
        float4 d = h4_to_f4(__ldcg(&G[g_csr[i + 3] * 32 + lane]));
        A1.x += a.x; A1.y += a.y; A1.z += a.z; A1.w += a.w;
        A2.x += b.x; A2.y += b.y; A2.z += b.z; A2.w += b.w;
        A3.x += c.x; A3.y += c.y; A3.z += c.z; A3.w += c.w;
        A4.x += d.x; A4.y += d.y; A4.z += d.z; A4.w += d.w;
    }
    for (; i < re; i++) {
        float4 a = h4_to_f4(__ldcg(&G[g_csr[i] * 32 + lane]));
        A1.x += a.x; A1.y += a.y; A1.z += a.z; A1.w += a.w;
    }
    A1.x += A2.x + A3.x + A4.x; A1.y += A2.y + A3.y + A4.y;
    A1.z += A2.z + A3.z + A4.z; A1.w += A2.w + A3.w + A4.w;
    float di = g_dinv[wid];
    float4 b = ((const float4*)b2)[lane];
    float4 w = ((const float4*)Wf)[lane];
    float s = fmaxf(A1.x * di + b.x, 0.f) * w.x
            + fmaxf(A1.y * di + b.y, 0.f) * w.y
            + fmaxf(A1.z * di + b.z, 0.f) * w.z
            + fmaxf(A1.w * di + b.w, 0.f) * w.w;
#pragma unroll
    for (int off = 16; off > 0; off >>= 1)
        s += __shfl_down_sync(0xFFFFFFFFu, s, off);
    if (lane == 0) out[wid] = s + __ldg(&bf[0]);
}

extern "C" void kernel_launch(void* const* d_in, const int* in_sizes, int n_in,
                              void* d_out, int out_size) {
    const int*   x    = (const int*)d_in[0];
    const int*   ei   = (const int*)d_in[1];
    const float* emb  = (const float*)d_in[2];
    const float* W1   = (const float*)d_in[3];
    const float* b1   = (const float*)d_in[4];
    const float* W2   = (const float*)d_in[5];
    const float* b2   = (const float*)d_in[6];
    const float* Wf   = (const float*)d_in[7];
    const float* bf   = (const float*)d_in[8];
    float* out = (float*)d_out;

    int n = in_sizes[0];           // 100000
    int e = in_sizes[1] / 2;       // 800000
    int V = in_sizes[2] / D;       // 1000
    const int* src = ei;
    const int* dst = ei + e;

    int tb = 256;
    int edgeBlocks     = (e + tb - 1) / tb;
    int edgeB2         = (e + tb * 2 - 1) / (tb * 2);
    int nodeWarpBlocks = (n * 32 + tb - 1) / tb;
    int scanBlocks     = (n + SCAN_ITEMS - 1) / SCAN_ITEMS;   // 98 <= 148: all resident

    void* degPtr;
    cudaGetSymbolAddress(&degPtr, g_deg);

    // CSR build + dinv + pack + weights prep (4 nodes)
    cudaMemsetAsync(degPtr, 0, (size_t)n * sizeof(int));
    k_deg<<<edgeB2, tb>>>(dst, e);
    k_scanprep<<<scanBlocks, tb>>>(emb, W1, W2, x, n, e, V, scanBlocks);
    k_fill<<<edgeBlocks, tb>>>(src, dst, e);

    // layer 1: fused gather + aggregate + finalize -> fp16
    k_agg1<<<nodeWarpBlocks, tb>>>(b1, n);

    // layer 2: fp16 gemm + fused aggregate/final dot
    k_gemm<<<(n + 127) / 128, 256>>>(n);
    k_agg2<<<nodeWarpBlocks, tb>>>(b2, Wf, bf, out, n);
}

// round 15
// speedup vs baseline: 1.1476x; 1.1476x over previous
#include <cuda_runtime.h>
#include <cuda_bf16.h>
#include <cuda_fp16.h>
#include <cstdint>

#define D 128
#define NMAX 100000
#define EMAX 800000
#define VMAX 1000
#define SCAN_ITEMS 1024
#define SCAN_MAXB  ((NMAX + SCAN_ITEMS - 1) / SCAN_ITEMS + 1)

// Scratch (allocation-free rule: device globals)
__device__ __align__(16) __half g_bufAh[NMAX * D];  // g2 vectors, fp16
__device__ __align__(16) __half g_bufCh[NMAX * D];  // h1 (post relu), fp16
__device__ __align__(16) __half g_embWh[VMAX * D];  // emb @ W1, fp16
__device__ __align__(16) __half g_W2t[D * D];       // W2 transposed [n][k], fp16
__device__ float g_dinv[NMAX];
__device__ int2  g_xd[NMAX];                        // packed {x[i], bits(dinv[i])}
__device__ int2  g_csrxd[EMAX];                     // per-CSR-slot {x[src], bits(dinv[src])}
__device__ int   g_deg[NMAX];
__device__ int   g_rowstart[NMAX + 1];
__device__ int   g_pos[EMAX];                       // per-edge rank within dst bucket
__device__ int   g_csr[EMAX];                       // src ids grouped by dst (for agg2)
__device__ int   g_bsum[SCAN_MAXB];
__device__ int   g_bsumx[SCAN_MAXB];

// ---------------- zero deg ----------------
__global__ void k_zero(int n) {
    int i = blockIdx.x * blockDim.x + threadIdx.x;
    if (i < n) g_deg[i] = 0;
}

// ---------------- degree count + per-edge rank ----------------
__global__ void k_deg(const int* __restrict__ dst, int e) {
    int i = blockIdx.x * blockDim.x + threadIdx.x;
    if (i < e) g_pos[i] = atomicAdd(&g_deg[dst[i]], 1);
}

// ---------------- scan phase A ----------------
__device__ __forceinline__ int4 load_deg4(int idx, int n) {
    int4 v = make_int4(0, 0, 0, 0);
    if (idx + 3 < n)      v = ((const int4*)g_deg)[idx >> 2];
    else {
        if (idx + 0 < n) v.x = g_deg[idx + 0];
        if (idx + 1 < n) v.y = g_deg[idx + 1];
        if (idx + 2 < n) v.z = g_deg[idx + 2];
        if (idx + 3 < n) v.w = g_deg[idx + 3];
    }
    return v;
}

__global__ void k_blocksum(int n) {
    __shared__ int sw[8];
    int t = threadIdx.x;
    int idx = blockIdx.x * SCAN_ITEMS + t * 4;
    int4 v = load_deg4(idx, n);
    int s = v.x + v.y + v.z + v.w;
#pragma unroll
    for (int off = 16; off > 0; off >>= 1) s += __shfl_down_sync(~0u, s, off);
    if ((t & 31) == 0) sw[t >> 5] = s;
    __syncthreads();
    if (t < 8) {
        int r = sw[t];
#pragma unroll
        for (int off = 4; off > 0; off >>= 1) r += __shfl_down_sync(0xFFu, r, off);
        if (t == 0) g_bsum[blockIdx.x] = r;
    }
}

// ---------------- scan phase B: parallel 128-wide scan (nb <= 128) ----------------
__global__ void k_scanbsum(int nb, int n, int e) {
    __shared__ int sp[128];
    int t = threadIdx.x;
    int v = (t < nb) ? g_bsum[t] : 0;
    sp[t] = v;
    __syncthreads();
#pragma unroll
    for (int off = 1; off < 128; off <<= 1) {
        int u = (t >= off) ? sp[t - off] : 0;
        __syncthreads();
        sp[t] += u;
        __syncthreads();
    }
    if (t < nb) g_bsumx[t] = sp[t] - v;   // exclusive
    if (t == 0) g_rowstart[n] = e;
}

// ---------------- scan phase C: rowstart + dinv + pack{x,dinv} ----------------
__global__ void k_scanout(const int* __restrict__ x, int n) {
    __shared__ int sp[256];
    int t = threadIdx.x;
    int idx = blockIdx.x * SCAN_ITEMS + t * 4;
    int4 v = load_deg4(idx, n);
    int s = v.x + v.y + v.z + v.w;
    sp[t] = s;
    __syncthreads();
    for (int off = 1; off < 256; off <<= 1) {
        int u = (t >= off) ? sp[t - off] : 0;
        __syncthreads();
        sp[t] += u;
        __syncthreads();
    }
    int pre = g_bsumx[blockIdx.x] + ((t == 0) ? 0 : sp[t - 1]);
    if (idx + 0 < n) { float di = rsqrtf((float)(v.x + 1)); g_rowstart[idx + 0] = pre; pre += v.x; g_dinv[idx + 0] = di; g_xd[idx + 0] = make_int2(x[idx + 0], __float_as_int(di)); }
    if (idx + 1 < n) { float di = rsqrtf((float)(v.y + 1)); g_rowstart[idx + 1] = pre; pre += v.y; g_dinv[idx + 1] = di; g_xd[idx + 1] = make_int2(x[idx + 1], __float_as_int(di)); }
    if (idx + 2 < n) { float di = rsqrtf((float)(v.z + 1)); g_rowstart[idx + 2] = pre; pre += v.z; g_dinv[idx + 2] = di; g_xd[idx + 2] = make_int2(x[idx + 2], __float_as_int(di)); }
    if (idx + 3 < n) { float di = rsqrtf((float)(v.w + 1)); g_rowstart[idx + 3] = pre;             g_dinv[idx + 3] = di; g_xd[idx + 3] = make_int2(x[idx + 3], __float_as_int(di)); }
}

// ---------------- CSR fill: NO atomics; also materialize csrxd = xd[src] ----------------
__global__ void k_fill(const int* __restrict__ src, const int* __restrict__ dst, int e) {
    int i = blockIdx.x * blockDim.x + threadIdx.x;
    if (i < e) {
        int s = src[i];
        int d = dst[i];
        int p = g_rowstart[d] + g_pos[i];
        g_csr[p] = s;
        g_csrxd[p] = g_xd[s];
    }
}

// ---------------- embW = emb @ W1 (V x D, tiny), fp16 output ----------------
__global__ void k_embw(const float* __restrict__ emb, const float* __restrict__ W) {
    __shared__ float se[D];
    int r = blockIdx.x;
    int c = threadIdx.x;
    se[c] = emb[r * D + c];
    __syncthreads();
    float acc = 0.f;
#pragma unroll
    for (int k = 0; k < D; k++) acc += se[k] * __ldg(&W[k * D + c]);
    g_embWh[r * D + c] = __float2half(acc);
}

// ---------------- W2 -> fp16 transposed [n][k] ----------------
__global__ void k_w2h(const float* __restrict__ W2) {
    int idx = blockIdx.x * blockDim.x + threadIdx.x;   // 16384
    int k = idx >> 7, nn = idx & 127;
    g_W2t[nn * D + k] = __float2half(W2[idx]);
}

// ---------------- helpers ----------------
__device__ __forceinline__ float4 h4_to_f4(uint2 u) {
    __half2 h01 = *(__half2*)&u.x;
    __half2 h23 = *(__half2*)&u.y;
    float2 f01 = __half22float2(h01);
    float2 f23 = __half22float2(h23);
    return make_float4(f01.x, f01.y, f23.x, f23.y);
}

// ---------------- fused layer1: gather-from-embW(fp16) via csrxd + finalize -> fp16 ----------------
__global__ void k_agg1(const float* __restrict__ b1, int n) {
    int wid  = (blockIdx.x * blockDim.x + threadIdx.x) >> 5;
    int lane = threadIdx.x & 31;
    if (wid >= n) return;
    const uint2* EW = (const uint2*)g_embWh;
    int2 sxd = g_xd[wid];
    float dis = __int_as_float(sxd.y);
    float4 e0 = h4_to_f4(EW[sxd.x * 32 + lane]);
    float4 A1 = make_float4(e0.x * dis, e0.y * dis, e0.z * dis, e0.w * dis);
    float4 A2 = make_float4(0.f, 0.f, 0.f, 0.f);
    float4 A3 = make_float4(0.f, 0.f, 0.f, 0.f);
    float4 A4 = make_float4(0.f, 0.f, 0.f, 0.f);
    int rs = g_rowstart[wid], re = g_rowstart[wid + 1];
    int i = rs;
    for (; i + 3 < re; i += 4) {
        int2 xd0 = g_csrxd[i];         // sequential/broadcast: L1-hit
        int2 xd1 = g_csrxd[i + 1];
        int2 xd2 = g_csrxd[i + 2];
        int2 xd3 = g_csrxd[i + 3];
        float4 a = h4_to_f4(EW[xd0.x * 32 + lane]);
        float4 b = h4_to_f4(EW[xd1.x * 32 + lane]);
        float4 c = h4_to_f4(EW[xd2.x * 32 + lane]);
        float4 d = h4_to_f4(EW[xd3.x * 32 + lane]);
        float d0 = __int_as_float(xd0.y), d1 = __int_as_float(xd1.y);
        float d2 = __int_as_float(xd2.y), d3 = __int_as_float(xd3.y);
        A1.x = fmaf(a.x, d0, A1.x); A1.y = fmaf(a.y, d0, A1.y); A1.z = fmaf(a.z, d0, A1.z); A1.w = fmaf(a.w, d0, A1.w);
        A2.x = fmaf(b.x, d1, A2.x); A2.y = fmaf(b.y, d1, A2.y); A2.z = fmaf(b.z, d1, A2.z); A2.w = fmaf(b.w, d1, A2.w);
        A3.x = fmaf(c.x, d2, A3.x); A3.y = fmaf(c.y, d2, A3.y); A3.z = fmaf(c.z, d2, A3.z); A3.w = fmaf(c.w, d2, A3.w);
        A4.x = fmaf(d.x, d3, A4.x); A4.y = fmaf(d.y, d3, A4.y); A4.z = fmaf(d.z, d3, A4.z); A4.w = fmaf(d.w, d3, A4.w);
    }
    for (; i < re; i++) {
        int2 xd0 = g_csrxd[i];
        float d0 = __int_as_float(xd0.y);
        float4 a = h4_to_f4(EW[xd0.x * 32 + lane]);
        A1.x = fmaf(a.x, d0, A1.x); A1.y = fmaf(a.y, d0, A1.y);
        A1.z = fmaf(a.z, d0, A1.z); A1.w = fmaf(a.w, d0, A1.w);
    }
    A1.x += A2.x + A3.x + A4.x; A1.y += A2.y + A3.y + A4.y;
    A1.z += A2.z + A3.z + A4.z; A1.w += A2.w + A3.w + A4.w;
    float4 b = ((const float4*)b1)[lane];
    float hx = fmaxf(A1.x * dis + b.x, 0.f);
    float hy = fmaxf(A1.y * dis + b.y, 0.f);
    float hz = fmaxf(A1.z * dis + b.z, 0.f);
    float hw = fmaxf(A1.w * dis + b.w, 0.f);
    __half2 lo = __floats2half2_rn(hx, hy);
    __half2 hi = __floats2half2_rn(hz, hw);
    uint2 o; o.x = *(uint32_t*)&lo; o.y = *(uint32_t*)&hi;
    ((uint2*)g_bufCh)[wid * 32 + lane] = o;
}

// ---------------- fp16 tensor-core GEMM: g2 = (h1 @ W2) * dinv -> fp16 ----------------
#define SR 72
__global__ void __launch_bounds__(256, 2) k_gemm(int n) {
    __shared__ __half sH[128 * SR];
    __shared__ __half sWt[128 * SR];
    int t = threadIdx.x;
    int warp = t >> 5, lane = t & 31;
    int g = lane >> 2, tg = lane & 3;
    int row0 = blockIdx.x * 128;
    int warpRow = warp * 16;

    float c[16][4];
#pragma unroll
    for (int nt = 0; nt < 16; nt++)
#pragma unroll
        for (int j = 0; j < 4; j++) c[nt][j] = 0.f;

    const uint4* Hv = (const uint4*)g_bufCh;
    const uint4* Wv = (const uint4*)g_W2t;

    for (int kc = 0; kc < 2; kc++) {
#pragma unroll
        for (int i = 0; i < 4; i++) {
            int idx = t + i * 256;
            int nn = idx >> 3, q = idx & 7;
            *(uint4*)&sWt[nn * SR + q * 8] = Wv[nn * 16 + kc * 8 + q];
        }
#pragma unroll
        for (int i = 0; i < 4; i++) {
            int idx = t + i * 256;
            int r = idx >> 3, q = idx & 7;
            int grow = row0 + r;
            uint4 v = make_uint4(0, 0, 0, 0);
            if (grow < n) v = Hv[grow * 16 + kc * 8 + q];
            *(uint4*)&sH[r * SR + q * 8] = v;
        }
        __syncthreads();
#pragma unroll
        for (int ks = 0; ks < 4; ks++) {
            int k0 = ks * 16;
            uint32_t a0 = *(uint32_t*)&sH[(warpRow + g)     * SR + k0 + 2 * tg];
            uint32_t a1 = *(uint32_t*)&sH[(warpRow + g + 8) * SR + k0 + 2 * tg];
            uint32_t a2 = *(uint32_t*)&sH[(warpRow + g)     * SR + k0 + 2 * tg + 8];
            uint32_t a3 = *(uint32_t*)&sH[(warpRow + g + 8) * SR + k0 + 2 * tg + 8];
#pragma unroll
            for (int nt = 0; nt < 16; nt++) {
                uint32_t b0 = *(uint32_t*)&sWt[(nt * 8 + g) * SR + k0 + 2 * tg];
                uint32_t b1 = *(uint32_t*)&sWt[(nt * 8 + g) * SR + k0 + 2 * tg + 8];
                asm volatile(
                    "mma.sync.aligned.m16n8k16.row.col.f32.f16.f16.f32 "
                    "{%0,%1,%2,%3}, {%4,%5,%6,%7}, {%8,%9}, {%0,%1,%2,%3};"
                    : "+f"(c[nt][0]), "+f"(c[nt][1]), "+f"(c[nt][2]), "+f"(c[nt][3])
                    : "r"(a0), "r"(a1), "r"(a2), "r"(a3), "r"(b0), "r"(b1));
            }
        }
        __syncthreads();
    }
    int r0 = row0 + warpRow + g;
    int r1 = r0 + 8;
    float di0 = (r0 < n) ? g_dinv[r0] : 0.f;
    float di1 = (r1 < n) ? g_dinv[r1] : 0.f;
    __half2* Bh = (__half2*)g_bufAh;
#pragma unroll
    for (int nt = 0; nt < 16; nt++) {
        int col = nt * 8 + tg * 2;
        if (r0 < n) Bh[(r0 * D + col) >> 1] = __floats2half2_rn(c[nt][0] * di0, c[nt][1] * di0);
        if (r1 < n) Bh[(r1 * D + col) >> 1] = __floats2half2_rn(c[nt][2] * di1, c[nt][3] * di1);
    }
}

// ---------------- fused aggregate layer2 (fp16 L2-only reads, 4-way) + final dot ----------------
__global__ void k_agg2(const float* __restrict__ b2, const float* __restrict__ Wf,
                       const float* __restrict__ bf, float* __restrict__ out, int n) {
    int wid  = (blockIdx.x * blockDim.x + threadIdx.x) >> 5;
    int lane = threadIdx.x & 31;
    if (wid >= n) return;
    const uint2* G = (const uint2*)g_bufAh;
    float4 A1 = h4_to_f4(__ldcg(&G[wid * 32 + lane]));
    float4 A2 = make_float4(0.f, 0.f, 0.f, 0.f);
    float4 A3 = make_float4(0.f, 0.f, 0.f, 0.f);
    float4 A4 = make_float4(0.f, 0.f, 0.f, 0.f);
    int rs = g_rowstart[wid], re = g_rowstart[wid + 1];
    int i = rs;
    for (; i + 3 < re; i += 4) {
        float4 a = h4_to_f4(__ldcg(&G[g_csr[i]     * 32 + lane]));
        float4 b = h4_to_f4(__ldcg(&G[g_csr[i + 1] * 32 + lane]));
        float4 c = h4_to_f4(__ldcg(&G[g_csr[i + 2] * 32 + lane]));
        float4 d = h4_to_f4(__ldcg(&G[g_csr[i + 3] * 32 + lane]));
        A1.x += a.x; A1.y += a.y; A1.z += a.z; A1.w += a.w;
        A2.x += b.x; A2.y += b.y; A2.z += b.z; A2.w += b.w;
        A3.x += c.x; A3.y += c.y; A3.z += c.z; A3.w += c.w;
        A4.x += d.x; A4.y += d.y; A4.z += d.z; A4.w += d.w;
    }
    for (; i < re; i++) {
        float4 a = h4_to_f4(__ldcg(&G[g_csr[i] * 32 + lane]));
        A1.x += a.x; A1.y += a.y; A1.z += a.z; A1.w += a.w;
    }
    A1.x += A2.x + A3.x + A4.x; A1.y += A2.y + A3.y + A4.y;
    A1.z += A2.z + A3.z + A4.z; A1.w += A2.w + A3.w + A4.w;
    float di = g_dinv[wid];
    float4 b = ((const float4*)b2)[lane];
    float4 w = ((const float4*)Wf)[lane];
    float s = fmaxf(A1.x * di + b.x, 0.f) * w.x
            + fmaxf(A1.y * di + b.y, 0.f) * w.y
            + fmaxf(A1.z * di + b.z, 0.f) * w.z
            + fmaxf(A1.w * di + b.w, 0.f) * w.w;
#pragma unroll
    for (int off = 16; off > 0; off >>= 1)
        s += __shfl_down_sync(0xFFFFFFFFu, s, off);
    if (lane == 0) out[wid] = s + __ldg(&bf[0]);
}

extern "C" void kernel_launch(void* const* d_in, const int* in_sizes, int n_in,
                              void* d_out, int out_size) {
    const int*   x    = (const int*)d_in[0];
    const int*   ei   = (const int*)d_in[1];
    const float* emb  = (const float*)d_in[2];
    const float* W1   = (const float*)d_in[3];
    const float* b1   = (const float*)d_in[4];
    const float* W2   = (const float*)d_in[5];
    const float* b2   = (const float*)d_in[6];
    const float* Wf   = (const float*)d_in[7];
    const float* bf   = (const float*)d_in[8];
    float* out = (float*)d_out;

    int n = in_sizes[0];           // 100000
    int e = in_sizes[1] / 2;       // 800000
    int V = in_sizes[2] / D;       // 1000
    const int* src = ei;
    const int* dst = ei + e;

    int tb = 256;
    int nodeBlocks     = (n + tb - 1) / tb;
    int edgeBlocks     = (e + tb - 1) / tb;
    int nodeWarpBlocks = (n * 32 + tb - 1) / tb;
    int scanBlocks     = (n + SCAN_ITEMS - 1) / SCAN_ITEMS;

    // CSR build + dinv + pack
    k_zero<<<nodeBlocks, tb>>>(n);
    k_deg<<<edgeBlocks, tb>>>(dst, e);
    k_blocksum<<<scanBlocks, 256>>>(n);
    k_scanbsum<<<1, 128>>>(scanBlocks, n, e);
    k_scanout<<<scanBlocks, 256>>>(x, n);
    k_fill<<<edgeBlocks, tb>>>(src, dst, e);

    // weights prep (small)
    k_embw<<<V, D>>>(emb, W1);
    k_w2h<<<(D * D) / 256, 256>>>(W2);

    // layer 1: fused gather + aggregate + finalize -> fp16
    k_agg1<<<nodeWarpBlocks, tb>>>(b1, n);

    // layer 2: fp16 gemm + fused aggregate/final dot
    k_gemm<<<(n + 127) / 128, 256>>>(n);
    k_agg2<<<nodeWarpBlocks, tb>>>(b2, Wf, bf, out, n);
}

// round 16
// speedup vs baseline: 1.1773x; 1.0258x over previous
#include <cuda_runtime.h>
#include <cuda_bf16.h>
#include <cuda_fp16.h>
#include <cstdint>

#define D 128
#define NMAX 100000
#define EMAX 800000
#define VMAX 1000
#define SCAN_ITEMS 1024
#define SCAN_MAXB  ((NMAX + SCAN_ITEMS - 1) / SCAN_ITEMS + 1)

// Scratch (allocation-free rule: device globals)
__device__ __align__(16) __half g_bufAh[NMAX * D];  // g2 vectors, fp16
__device__ __align__(16) __half g_bufCh[NMAX * D];  // h1 (post relu), fp16
__device__ __align__(16) __half g_embWh[VMAX * D];  // emb @ W1, fp16
__device__ __align__(16) __half g_W2t[D * D];       // W2 transposed [n][k], fp16
__device__ float g_dinv[NMAX];
__device__ int2  g_xd[NMAX];                        // packed {x[i], bits(dinv[i])}
__device__ int2  g_csrxd[EMAX];                     // per-CSR-slot {x[src], bits(dinv[src])}
__device__ int   g_deg[NMAX];
__device__ int   g_rowstart[NMAX + 1];
__device__ int   g_pos[EMAX];                       // per-edge rank within dst bucket
__device__ int   g_csr[EMAX];                       // src ids grouped by dst (for agg2)
__device__ int   g_bsum[SCAN_MAXB];

// ---------------- zero deg ----------------
__global__ void k_zero(int n) {
    int i = blockIdx.x * blockDim.x + threadIdx.x;
    if (i < n) g_deg[i] = 0;
}

// ---------------- degree count + per-edge rank ----------------
__global__ void k_deg(const int* __restrict__ dst, int e) {
    int i = blockIdx.x * blockDim.x + threadIdx.x;
    if (i < e) g_pos[i] = atomicAdd(&g_deg[dst[i]], 1);
}

// ---------------- scan phase A ----------------
__device__ __forceinline__ int4 load_deg4(int idx, int n) {
    int4 v = make_int4(0, 0, 0, 0);
    if (idx + 3 < n)      v = ((const int4*)g_deg)[idx >> 2];
    else {
        if (idx + 0 < n) v.x = g_deg[idx + 0];
        if (idx + 1 < n) v.y = g_deg[idx + 1];
        if (idx + 2 < n) v.z = g_deg[idx + 2];
        if (idx + 3 < n) v.w = g_deg[idx + 3];
    }
    return v;
}

__global__ void k_blocksum(int n) {
    __shared__ int sw[8];
    int t = threadIdx.x;
    int idx = blockIdx.x * SCAN_ITEMS + t * 4;
    int4 v = load_deg4(idx, n);
    int s = v.x + v.y + v.z + v.w;
#pragma unroll
    for (int off = 16; off > 0; off >>= 1) s += __shfl_down_sync(~0u, s, off);
    if ((t & 31) == 0) sw[t >> 5] = s;
    __syncthreads();
    if (t < 8) {
        int r = sw[t];
#pragma unroll
        for (int off = 4; off > 0; off >>= 1) r += __shfl_down_sync(0xFFu, r, off);
        if (t == 0) g_bsum[blockIdx.x] = r;
    }
}

// ---------------- scan phase B+C fused: each block reduces bsum prefix itself ----------------
__global__ void k_scanout(const int* __restrict__ x, int n, int e) {
    __shared__ int sp[256];
    __shared__ int sred[8];
    __shared__ int soff;
    int t = threadIdx.x;
    int bid = blockIdx.x;
    // block offset = sum of bsum[0..bid) ; bid <= 97 < 256
    {
        int val = (t < bid) ? g_bsum[t] : 0;
#pragma unroll
        for (int off = 16; off > 0; off >>= 1) val += __shfl_down_sync(~0u, val, off);
        if ((t & 31) == 0) sred[t >> 5] = val;
        __syncthreads();
        if (t == 0) {
            int s = 0;
#pragma unroll
            for (int w = 0; w < 8; w++) s += sred[w];
            soff = s;
        }
        __syncthreads();
    }
    int blockOff = soff;

    int idx = bid * SCAN_ITEMS + t * 4;
    int4 v = load_deg4(idx, n);
    int s = v.x + v.y + v.z + v.w;
    sp[t] = s;
    __syncthreads();
    for (int off = 1; off < 256; off <<= 1) {
        int u = (t >= off) ? sp[t - off] : 0;
        __syncthreads();
        sp[t] += u;
        __syncthreads();
    }
    int pre = blockOff + ((t == 0) ? 0 : sp[t - 1]);
    if (idx + 0 < n) { float di = rsqrtf((float)(v.x + 1)); g_rowstart[idx + 0] = pre; pre += v.x; g_dinv[idx + 0] = di; g_xd[idx + 0] = make_int2(x[idx + 0], __float_as_int(di)); }
    if (idx + 1 < n) { float di = rsqrtf((float)(v.y + 1)); g_rowstart[idx + 1] = pre; pre += v.y; g_dinv[idx + 1] = di; g_xd[idx + 1] = make_int2(x[idx + 1], __float_as_int(di)); }
    if (idx + 2 < n) { float di = rsqrtf((float)(v.z + 1)); g_rowstart[idx + 2] = pre; pre += v.z; g_dinv[idx + 2] = di; g_xd[idx + 2] = make_int2(x[idx + 2], __float_as_int(di)); }
    if (idx + 3 < n) { float di = rsqrtf((float)(v.w + 1)); g_rowstart[idx + 3] = pre;             g_dinv[idx + 3] = di; g_xd[idx + 3] = make_int2(x[idx + 3], __float_as_int(di)); }
    if (bid == 0 && t == 0) g_rowstart[n] = e;
}

// ---------------- CSR fill: NO atomics; also materialize csrxd = xd[src] ----------------
__global__ void k_fill(const int* __restrict__ src, const int* __restrict__ dst, int e) {
    int i = blockIdx.x * blockDim.x + threadIdx.x;
    if (i < e) {
        int s = src[i];
        int d = dst[i];
        int p = g_rowstart[d] + g_pos[i];
        g_csr[p] = s;
        g_csrxd[p] = g_xd[s];
    }
}

// ---------------- merged prep: blocks [0,V): embW row; [V, V+128): W2t ----------------
__global__ void k_prep(const float* __restrict__ emb, const float* __restrict__ W1,
                       const float* __restrict__ W2, int V) {
    int b = blockIdx.x;
    int t = threadIdx.x;           // 128 threads
    if (b < V) {
        __shared__ float se[D];
        se[t] = emb[b * D + t];
        __syncthreads();
        float acc = 0.f;
#pragma unroll
        for (int k = 0; k < D; k++) acc += se[k] * __ldg(&W1[k * D + t]);
        g_embWh[b * D + t] = __float2half(acc);
    } else {
        int idx = (b - V) * 128 + t;   // 128 blocks x 128 threads = 16384
        int k = idx >> 7, nn = idx & 127;
        g_W2t[nn * D + k] = __float2half(W2[idx]);
    }
}

// ---------------- helpers ----------------
__device__ __forceinline__ float4 h4_to_f4(uint2 u) {
    __half2 h01 = *(__half2*)&u.x;
    __half2 h23 = *(__half2*)&u.y;
    float2 f01 = __half22float2(h01);
    float2 f23 = __half22float2(h23);
    return make_float4(f01.x, f01.y, f23.x, f23.y);
}

// ---------------- fused layer1: gather-from-embW(fp16) via csrxd, 8-way MLP ----------------
__global__ void k_agg1(const float* __restrict__ b1, int n) {
    int wid  = (blockIdx.x * blockDim.x + threadIdx.x) >> 5;
    int lane = threadIdx.x & 31;
    if (wid >= n) return;
    const uint2* EW = (const uint2*)g_embWh;
    int2 sxd = g_xd[wid];
    float dis = __int_as_float(sxd.y);
    float4 e0 = h4_to_f4(EW[sxd.x * 32 + lane]);
    float4 A1 = make_float4(e0.x * dis, e0.y * dis, e0.z * dis, e0.w * dis);
    float4 A2 = make_float4(0.f, 0.f, 0.f, 0.f);
    float4 A3 = make_float4(0.f, 0.f, 0.f, 0.f);
    float4 A4 = make_float4(0.f, 0.f, 0.f, 0.f);
    int rs = g_rowstart[wid], re = g_rowstart[wid + 1];
    int i = rs;
    for (; i + 7 < re; i += 8) {
        int2 xd0 = g_csrxd[i];
        int2 xd1 = g_csrxd[i + 1];
        int2 xd2 = g_csrxd[i + 2];
        int2 xd3 = g_csrxd[i + 3];
        int2 xd4 = g_csrxd[i + 4];
        int2 xd5 = g_csrxd[i + 5];
        int2 xd6 = g_csrxd[i + 6];
        int2 xd7 = g_csrxd[i + 7];
        uint2 u0 = EW[xd0.x * 32 + lane];
        uint2 u1 = EW[xd1.x * 32 + lane];
        uint2 u2 = EW[xd2.x * 32 + lane];
        uint2 u3 = EW[xd3.x * 32 + lane];
        uint2 u4 = EW[xd4.x * 32 + lane];
        uint2 u5 = EW[xd5.x * 32 + lane];
        uint2 u6 = EW[xd6.x * 32 + lane];
        uint2 u7 = EW[xd7.x * 32 + lane];
        float4 a = h4_to_f4(u0); float d0 = __int_as_float(xd0.y);
        float4 b = h4_to_f4(u1); float d1 = __int_as_float(xd1.y);
        float4 c = h4_to_f4(u2); float d2 = __int_as_float(xd2.y);
        float4 d = h4_to_f4(u3); float d3 = __int_as_float(xd3.y);
        A1.x = fmaf(a.x, d0, A1.x); A1.y = fmaf(a.y, d0, A1.y); A1.z = fmaf(a.z, d0, A1.z); A1.w = fmaf(a.w, d0, A1.w);
        A2.x = fmaf(b.x, d1, A2.x); A2.y = fmaf(b.y, d1, A2.y); A2.z = fmaf(b.z, d1, A2.z); A2.w = fmaf(b.w, d1, A2.w);
        A3.x = fmaf(c.x, d2, A3.x); A3.y = fmaf(c.y, d2, A3.y); A3.z = fmaf(c.z, d2, A3.z); A3.w = fmaf(c.w, d2, A3.w);
        A4.x = fmaf(d.x, d3, A4.x); A4.y = fmaf(d.y, d3, A4.y); A4.z = fmaf(d.z, d3, A4.z); A4.w = fmaf(d.w, d3, A4.w);
        a = h4_to_f4(u4); d0 = __int_as_float(xd4.y);
        b = h4_to_f4(u5); d1 = __int_as_float(xd5.y);
        c = h4_to_f4(u6); d2 = __int_as_float(xd6.y);
        d = h4_to_f4(u7); d3 = __int_as_float(xd7.y);
        A1.x = fmaf(a.x, d0, A1.x); A1.y = fmaf(a.y, d0, A1.y); A1.z = fmaf(a.z, d0, A1.z); A1.w = fmaf(a.w, d0, A1.w);
        A2.x = fmaf(b.x, d1, A2.x); A2.y = fmaf(b.y, d1, A2.y); A2.z = fmaf(b.z, d1, A2.z); A2.w = fmaf(b.w, d1, A2.w);
        A3.x = fmaf(c.x, d2, A3.x); A3.y = fmaf(c.y, d2, A3.y); A3.z = fmaf(c.z, d2, A3.z); A3.w = fmaf(c.w, d2, A3.w);
        A4.x = fmaf(d.x, d3, A4.x); A4.y = fmaf(d.y, d3, A4.y); A4.z = fmaf(d.z, d3, A4.z); A4.w = fmaf(d.w, d3, A4.w);
    }
    for (; i + 3 < re; i += 4) {
        int2 xd0 = g_csrxd[i];
        int2 xd1 = g_csrxd[i + 1];
        int2 xd2 = g_csrxd[i + 2];
        int2 xd3 = g_csrxd[i + 3];
        float4 a = h4_to_f4(EW[xd0.x * 32 + lane]);
        float4 b = h4_to_f4(EW[xd1.x * 32 + lane]);
        float4 c = h4_to_f4(EW[xd2.x * 32 + lane]);
        float4 d = h4_to_f4(EW[xd3.x * 32 + lane]);
        float d0 = __int_as_float(xd0.y), d1 = __int_as_float(xd1.y);
        float d2 = __int_as_float(xd2.y), d3 = __int_as_float(xd3.y);
        A1.x = fmaf(a.x, d0, A1.x); A1.y = fmaf(a.y, d0, A1.y); A1.z = fmaf(a.z, d0, A1.z); A1.w = fmaf(a.w, d0, A1.w);
        A2.x = fmaf(b.x, d1, A2.x); A2.y = fmaf(b.y, d1, A2.y); A2.z = fmaf(b.z, d1, A2.z); A2.w = fmaf(b.w, d1, A2.w);
        A3.x = fmaf(c.x, d2, A3.x); A3.y = fmaf(c.y, d2, A3.y); A3.z = fmaf(c.z, d2, A3.z); A3.w = fmaf(c.w, d2, A3.w);
        A4.x = fmaf(d.x, d3, A4.x); A4.y = fmaf(d.y, d3, A4.y); A4.z = fmaf(d.z, d3, A4.z); A4.w = fmaf(d.w, d3, A4.w);
    }
    for (; i < re; i++) {
        int2 xd0 = g_csrxd[i];
        float d0 = __int_as_float(xd0.y);
        float4 a = h4_to_f4(EW[xd0.x * 32 + lane]);
        A1.x = fmaf(a.x, d0, A1.x); A1.y = fmaf(a.y, d0, A1.y);
        A1.z = fmaf(a.z, d0, A1.z); A1.w = fmaf(a.w, d0, A1.w);
    }
    A1.x += A2.x + A3.x + A4.x; A1.y += A2.y + A3.y + A4.y;
    A1.z += A2.z + A3.z + A4.z; A1.w += A2.w + A3.w + A4.w;
    float4 b = ((const float4*)b1)[lane];
    float hx = fmaxf(A1.x * dis + b.x, 0.f);
    float hy = fmaxf(A1.y * dis + b.y, 0.f);
    float hz = fmaxf(A1.z * dis + b.z, 0.f);
    float hw = fmaxf(A1.w * dis + b.w, 0.f);
    __half2 lo = __floats2half2_rn(hx, hy);
    __half2 hi = __floats2half2_rn(hz, hw);
    uint2 o; o.x = *(uint32_t*)&lo; o.y = *(uint32_t*)&hi;
    ((uint2*)g_bufCh)[wid * 32 + lane] = o;
}

// ---------------- fp16 tensor-core GEMM: g2 = (h1 @ W2) * dinv -> fp16 ----------------
#define SR 72
__global__ void __launch_bounds__(256, 2) k_gemm(int n) {
    __shared__ __half sH[128 * SR];
    __shared__ __half sWt[128 * SR];
    int t = threadIdx.x;
    int warp = t >> 5, lane = t & 31;
    int g = lane >> 2, tg = lane & 3;
    int row0 = blockIdx.x * 128;
    int warpRow = warp * 16;

    float c[16][4];
#pragma unroll
    for (int nt = 0; nt < 16; nt++)
#pragma unroll
        for (int j = 0; j < 4; j++) c[nt][j] = 0.f;

    const uint4* Hv = (const uint4*)g_bufCh;
    const uint4* Wv = (const uint4*)g_W2t;

    for (int kc = 0; kc < 2; kc++) {
#pragma unroll
        for (int i = 0; i < 4; i++) {
            int idx = t + i * 256;
            int nn = idx >> 3, q = idx & 7;
            *(uint4*)&sWt[nn * SR + q * 8] = Wv[nn * 16 + kc * 8 + q];
        }
#pragma unroll
        for (int i = 0; i < 4; i++) {
            int idx = t + i * 256;
            int r = idx >> 3, q = idx & 7;
            int grow = row0 + r;
            uint4 v = make_uint4(0, 0, 0, 0);
            if (grow < n) v = Hv[grow * 16 + kc * 8 + q];
            *(uint4*)&sH[r * SR + q * 8] = v;
        }
        __syncthreads();
#pragma unroll
        for (int ks = 0; ks < 4; ks++) {
            int k0 = ks * 16;
            uint32_t a0 = *(uint32_t*)&sH[(warpRow + g)     * SR + k0 + 2 * tg];
            uint32_t a1 = *(uint32_t*)&sH[(warpRow + g + 8) * SR + k0 + 2 * tg];
            uint32_t a2 = *(uint32_t*)&sH[(warpRow + g)     * SR + k0 + 2 * tg + 8];
            uint32_t a3 = *(uint32_t*)&sH[(warpRow + g + 8) * SR + k0 + 2 * tg + 8];
#pragma unroll
            for (int nt = 0; nt < 16; nt++) {
                uint32_t b0 = *(uint32_t*)&sWt[(nt * 8 + g) * SR + k0 + 2 * tg];
                uint32_t b1 = *(uint32_t*)&sWt[(nt * 8 + g) * SR + k0 + 2 * tg + 8];
                asm volatile(
                    "mma.sync.aligned.m16n8k16.row.col.f32.f16.f16.f32 "
                    "{%0,%1,%2,%3}, {%4,%5,%6,%7}, {%8,%9}, {%0,%1,%2,%3};"
                    : "+f"(c[nt][0]), "+f"(c[nt][1]), "+f"(c[nt][2]), "+f"(c[nt][3])
                    : "r"(a0), "r"(a1), "r"(a2), "r"(a3), "r"(b0), "r"(b1));
            }
        }
        __syncthreads();
    }
    int r0 = row0 + warpRow + g;
    int r1 = r0 + 8;
    float di0 = (r0 < n) ? g_dinv[r0] : 0.f;
    float di1 = (r1 < n) ? g_dinv[r1] : 0.f;
    __half2* Bh = (__half2*)g_bufAh;
#pragma unroll
    for (int nt = 0; nt < 16; nt++) {
        int col = nt * 8 + tg * 2;
        if (r0 < n) Bh[(r0 * D + col) >> 1] = __floats2half2_rn(c[nt][0] * di0, c[nt][1] * di0);
        if (r1 < n) Bh[(r1 * D + col) >> 1] = __floats2half2_rn(c[nt][2] * di1, c[nt][3] * di1);
    }
}

// ---------------- fused aggregate layer2 (fp16 L2-only reads, 4-way) + final dot ----------------
__global__ void k_agg2(const float* __restrict__ b2, const float* __restrict__ Wf,
                       const float* __restrict__ bf, float* __restrict__ out, int n) {
    int wid  = (blockIdx.x * blockDim.x + threadIdx.x) >> 5;
    int lane = threadIdx.x & 31;
    if (wid >= n) return;
    const uint2* G = (const uint2*)g_bufAh;
    float4 A1 = h4_to_f4(__ldcg(&G[wid * 32 + lane]));
    float4 A2 = make_float4(0.f, 0.f, 0.f, 0.f);
    float4 A3 = make_float4(0.f, 0.f, 0.f, 0.f);
    float4 A4 = make_float4(0.f, 0.f, 0.f, 0.f);
    int rs = g_rowstart[wid], re = g_rowstart[wid + 1];
    int i = rs;
    for (; i + 3 < re; i += 4) {
        float4 a = h4_to_f4(__ldcg(&G[g_csr[i]     * 32 + lane]));
        float4 b = h4_to_f4(__ldcg(&G[g_csr[i + 1] * 32 + lane]));
        float4 c = h4_to_f4(__ldcg(&G[g_csr[i + 2] * 32 + lane]));
        float4 d = h4_to_f4(__ldcg(&G[g_csr[i + 3] * 32 + lane]));
        A1.x += a.x; A1.y += a.y; A1.z += a.z; A1.w += a.w;
        A2.x += b.x; A2.y += b.y; A2.z += b.z; A2.w += b.w;
        A3.x += c.x; A3.y += c.y; A3.z += c.z; A3.w += c.w;
        A4.x += d.x; A4.y += d.y; A4.z += d.z; A4.w += d.w;
    }
    for (; i < re; i++) {
        float4 a = h4_to_f4(__ldcg(&G[g_csr[i] * 32 + lane]));
        A1.x += a.x; A1.y += a.y; A1.z += a.z; A1.w += a.w;
    }
    A1.x += A2.x + A3.x + A4.x; A1.y += A2.y + A3.y + A4.y;
    A1.z += A2.z + A3.z + A4.z; A1.w += A2.w + A3.w + A4.w;
    float di = g_dinv[wid];
    float4 b = ((const float4*)b2)[lane];
    float4 w = ((const float4*)Wf)[lane];
    float s = fmaxf(A1.x * di + b.x, 0.f) * w.x
            + fmaxf(A1.y * di + b.y, 0.f) * w.y
            + fmaxf(A1.z * di + b.z, 0.f) * w.z
            + fmaxf(A1.w * di + b.w, 0.f) * w.w;
#pragma unroll
    for (int off = 16; off > 0; off >>= 1)
        s += __shfl_down_sync(0xFFFFFFFFu, s, off);
    if (lane == 0) out[wid] = s + __ldg(&bf[0]);
}

extern "C" void kernel_launch(void* const* d_in, const int* in_sizes, int n_in,
                              void* d_out, int out_size) {
    const int*   x    = (const int*)d_in[0];
    const int*   ei   = (const int*)d_in[1];
    const float* emb  = (const float*)d_in[2];
    const float* W1   = (const float*)d_in[3];
    const float* b1   = (const float*)d_in[4];
    const float* W2   = (const float*)d_in[5];
    const float* b2   = (const float*)d_in[6];
    const float* Wf   = (const float*)d_in[7];
    const float* bf   = (const float*)d_in[8];
    float* out = (float*)d_out;

    int n = in_sizes[0];           // 100000
    int e = in_sizes[1] / 2;       // 800000
    int V = in_sizes[2] / D;       // 1000
    const int* src = ei;
    const int* dst = ei + e;

    int tb = 256;
    int nodeBlocks     = (n + tb - 1) / tb;
    int edgeBlocks     = (e + tb - 1) / tb;
    int nodeWarpBlocks = (n * 32 + tb - 1) / tb;
    int scanBlocks     = (n + SCAN_ITEMS - 1) / SCAN_ITEMS;

    // CSR build + dinv + pack
    k_zero<<<nodeBlocks, tb>>>(n);
    k_deg<<<edgeBlocks, tb>>>(dst, e);
    k_blocksum<<<scanBlocks, 256>>>(n);
    k_scanout<<<scanBlocks, 256>>>(x, n, e);
    k_fill<<<edgeBlocks, tb>>>(src, dst, e);

    // weights prep (merged embW + W2t)
    k_prep<<<V + 128, 128>>>(emb, W1, W2, V);

    // layer 1: fused gather + aggregate + finalize -> fp16
    k_agg1<<<nodeWarpBlocks, tb>>>(b1, n);

    // layer 2: fp16 gemm + fused aggregate/final dot
    k_gemm<<<(n + 127) / 128, 256>>>(n);
    k_agg2<<<nodeWarpBlocks, tb>>>(b2, Wf, bf, out, n);
}